// round 2
// baseline (speedup 1.0000x reference)
#include <cuda_runtime.h>
#include <cuda_bf16.h>

// Problem constants
#define NN   131072     // nodes per branch
#define GG   4096       // graphs
#define NPGC 32         // nodes per graph
#define EE   1048576    // edges per branch
#define SS   64         // state size
#define HH   128        // hidden size

// ---------------- device scratch (no allocs allowed) ----------------
__device__ int   g_is64;                 // 1 if edge_index is int64, 0 if int32
__device__ float g_wsrc[2][SS];          // W @ att_src per branch
__device__ float g_wdst[2][SS];          // W @ att_dst per branch
__device__ float g_adst[2][GG];          // a_dst at self node (32g+31) per graph
__device__ float g_num[2][GG][SS];       // sum_e p_e * x[src_e]
__device__ float g_den[2][GG];           // sum_e p_e

// ---------------- kernel 0: detect index dtype ----------------
__global__ void k_detect(const unsigned* up_edges_raw) {
    if (blockIdx.x == 0 && threadIdx.x == 0) {
        // If the buffer holds int64 values (< 2^31, non-negative), every odd
        // 32-bit word is 0. With int32 node ids, 64 consecutive odd words
        // being all zero has ~0 probability.
        int f = 1;
        for (int i = 0; i < 64; i++) {
            if (up_edges_raw[2 * i + 1] != 0u) { f = 0; break; }
        }
        g_is64 = f;
    }
}

// ---------------- kernel 1: zero accumulators ----------------
__global__ void k_zero() {
    int total = 2 * GG * SS;
    for (int i = blockIdx.x * blockDim.x + threadIdx.x; i < total;
         i += gridDim.x * blockDim.x) {
        ((float*)g_num)[i] = 0.0f;
    }
    int total2 = 2 * GG;
    for (int i = blockIdx.x * blockDim.x + threadIdx.x; i < total2;
         i += gridDim.x * blockDim.x) {
        ((float*)g_den)[i] = 0.0f;
    }
}

// ---------------- kernel 2: fold attention vectors through W ----------------
// w_src = W @ att_src  (length 64), same for dst; both branches. 256 threads.
__global__ void k_prep(const float* __restrict__ upW,
                       const float* __restrict__ up_as,
                       const float* __restrict__ up_ad,
                       const float* __restrict__ dnW,
                       const float* __restrict__ dn_as,
                       const float* __restrict__ dn_ad) {
    int t = threadIdx.x;           // 0..255
    int s = t & 63;
    int which = t >> 6;            // 0: up src, 1: up dst, 2: dn src, 3: dn dst
    const float* W = (which < 2) ? upW : dnW;
    const float* a = (which == 0) ? up_as : (which == 1) ? up_ad
                   : (which == 2) ? dn_as : dn_ad;
    float acc = 0.0f;
#pragma unroll 8
    for (int h = 0; h < HH; h++) acc += W[s * HH + h] * a[h];
    if (which == 0)      g_wsrc[0][s] = acc;
    else if (which == 1) g_wdst[0][s] = acc;
    else if (which == 2) g_wsrc[1][s] = acc;
    else                 g_wdst[1][s] = acc;
}

// ---------------- kernel 3: a_dst at self nodes ----------------
// one warp per (branch, graph): dot(x[32g+31], w_dst[branch])
__global__ void k_adst(const float* __restrict__ upx,
                       const float* __restrict__ dnx) {
    int w    = (blockIdx.x * blockDim.x + threadIdx.x) >> 5;
    int lane = threadIdx.x & 31;
    if (w >= 2 * GG) return;
    int b = w >> 12;               // /4096
    int g = w & (GG - 1);
    const float* x = b ? dnx : upx;
    float2 wv = ((const float2*)g_wdst[b])[lane];
    const float2* xr = (const float2*)(x + (long)(g * NPGC + NPGC - 1) * SS);
    float2 xv = xr[lane];
    float p = xv.x * wv.x + xv.y * wv.y;
#pragma unroll
    for (int o = 16; o; o >>= 1) p += __shfl_xor_sync(0xffffffffu, p, o);
    if (lane == 0) g_adst[b][g] = p;
}

// ---------------- kernel 4: edge scan + softmax-weighted x accumulation ----
// grid: (blocks, 2) — blockIdx.y selects branch. Warp-ballot compaction:
// each lane checks one edge; relevant edges (dst%32==31) are processed
// warp-cooperatively (dot + exp + 64+1 atomic adds).
__global__ void k_edges(const void* __restrict__ up_eidx,
                        const void* __restrict__ dn_eidx,
                        const float* __restrict__ upx,
                        const float* __restrict__ dnx) {
    int branch = blockIdx.y;
    const void*  eidx = branch ? dn_eidx : up_eidx;
    const float* x    = branch ? dnx    : upx;
    const int is64 = g_is64;

    int lane = threadIdx.x & 31;
    int warp = (blockIdx.x * blockDim.x + threadIdx.x) >> 5;
    int nwarps = (gridDim.x * blockDim.x) >> 5;

    float2 wv = ((const float2*)g_wsrc[branch])[lane];

    const int*       e32 = (const int*)eidx;
    const long long* e64 = (const long long*)eidx;

    for (long base = (long)warp * 32; base < EE; base += (long)nwarps * 32) {
        long i = base + lane;
        int dst = is64 ? (int)e64[EE + i] : e32[EE + i];
        bool rel = ((dst & 31) == 31);
        unsigned mask = __ballot_sync(0xffffffffu, rel);
        while (mask) {
            int l = __ffs(mask) - 1;
            mask &= mask - 1;
            int d = __shfl_sync(0xffffffffu, dst, l);
            long ei = base + l;
            int src = is64 ? (int)e64[ei] : e32[ei];   // broadcast load
            int g = d >> 5;

            float2 xv = ((const float2*)(x + (long)src * SS))[lane];
            float part = xv.x * wv.x + xv.y * wv.y;
#pragma unroll
            for (int o = 16; o; o >>= 1)
                part += __shfl_xor_sync(0xffffffffu, part, o);

            float e = part + g_adst[branch][g];
            e = (e > 0.0f) ? e : 0.2f * e;            // leaky_relu
            float p = __expf(e);

            float* num = g_num[branch][g];
            atomicAdd(num + 2 * lane,     p * xv.x);
            atomicAdd(num + 2 * lane + 1, p * xv.y);
            if (lane == 0) atomicAdd(&g_den[branch][g], p);
        }
    }
}

// ---------------- kernel 5: per-graph finish ----------------
// one block (128 threads) per graph:
//   xs = num/den ; h = xs@W + bias ; sigmoid ; prod ; dot mlp_W ; + mlp_b
__global__ void k_finish(const float* __restrict__ upW,
                         const float* __restrict__ upb,
                         const float* __restrict__ dnW,
                         const float* __restrict__ dnb,
                         const float* __restrict__ mlpW,
                         const float* __restrict__ mlpb,
                         float* __restrict__ out) {
    int g = blockIdx.x;
    int t = threadIdx.x;   // 0..127
    __shared__ float xs_up[SS];
    __shared__ float xs_dn[SS];
    __shared__ float red[HH];

    if (t < SS) {
        float du = g_den[0][g] + 1e-16f;
        float dd = g_den[1][g] + 1e-16f;
        xs_up[t] = g_num[0][g][t] / du;
        xs_dn[t] = g_num[1][g][t] / dd;
    }
    __syncthreads();

    float hu = upb[t];
    float hd = dnb[t];
#pragma unroll 8
    for (int s = 0; s < SS; s++) {
        hu += xs_up[s] * upW[s * HH + t];
        hd += xs_dn[s] * dnW[s * HH + t];
    }
    float su = 1.0f / (1.0f + expf(-hu));
    float sd = 1.0f / (1.0f + expf(-hd));
    red[t] = su * sd * mlpW[t];
    __syncthreads();
#pragma unroll
    for (int o = 64; o > 0; o >>= 1) {
        if (t < o) red[t] += red[t + o];
        __syncthreads();
    }
    if (t == 0) out[g] = red[0] + mlpb[0];
}

// ---------------- launch ----------------
extern "C" void kernel_launch(void* const* d_in, const int* in_sizes, int n_in,
                              void* d_out, int out_size) {
    const float* up_x     = (const float*)d_in[0];
    const void*  up_eidx  = d_in[1];
    // d_in[2] up_batch  — unused (batch layout is deterministic: arange/32)
    const float* dn_x     = (const float*)d_in[3];
    const void*  dn_eidx  = d_in[4];
    // d_in[5] down_batch — unused
    const float* upW      = (const float*)d_in[6];
    const float* up_as    = (const float*)d_in[7];
    const float* up_ad    = (const float*)d_in[8];
    const float* up_b     = (const float*)d_in[9];
    const float* dnW      = (const float*)d_in[10];
    const float* dn_as    = (const float*)d_in[11];
    const float* dn_ad    = (const float*)d_in[12];
    const float* dn_b     = (const float*)d_in[13];
    const float* mlpW     = (const float*)d_in[14];
    const float* mlpb     = (const float*)d_in[15];
    float* out = (float*)d_out;

    k_detect<<<1, 32>>>((const unsigned*)up_eidx);
    k_zero<<<520, 256>>>();
    k_prep<<<1, 256>>>(upW, up_as, up_ad, dnW, dn_as, dn_ad);
    k_adst<<<(2 * GG * 32 + 255) / 256, 256>>>(up_x, dn_x);
    {
        dim3 grid(592, 2);   // 592 blocks x 8 warps = 4736 warps/branch
        k_edges<<<grid, 256>>>(up_eidx, dn_eidx, up_x, dn_x);
    }
    k_finish<<<GG, HH>>>(upW, up_b, dnW, dn_b, mlpW, mlpb, out);
}